// round 12
// baseline (speedup 1.0000x reference)
#include <cuda_runtime.h>

constexpr int PB = 2, PC = 64, PH = 256, PW = 256, IMG = 512;

// Scratch (device globals)
__device__ float g_R[PB * 3 * PH * PW];   // resized img (3 ch)
__device__ float g_S[PB * PH * PW];       // sigmoid(inp . w_comp)
__device__ float g_PXo[32 * PW];          // pos basis [o][w]
__device__ float g_PYo[32 * PH];
__device__ float g_T1t[PH * PW];          // T1t[h][w] = sum_o PX[o,w]*PY[o,h]
__device__ float g_GX[3 * PW];
__device__ float g_GY[3 * PH];
__device__ float g_M[9];                  // w_img^T w_img
__device__ float g_phi[PB * 9 * PH * PW]; // per-neighbor weight, 4.7 MB

// ---------------------------------------------------------------------------
// K1: prep = pos basis (0..63) + sigmoid(S) (64..575) + resize (576..2111)
// ---------------------------------------------------------------------------
__device__ __forceinline__ void make_taps(int o, int* j, float* wt) {
    j[0] = 2 * o - 1; j[1] = 2 * o; j[2] = 2 * o + 1; j[3] = 2 * o + 2;
    wt[0] = 0.125f; wt[1] = 0.375f; wt[2] = 0.375f; wt[3] = 0.125f;
    if (o == 0) {
        j[0] = 0; wt[0] = 0.f;
        wt[1] = 3.f / 7.f; wt[2] = 3.f / 7.f; wt[3] = 1.f / 7.f;
    } else if (o == 255) {
        j[3] = 511; wt[3] = 0.f;
        wt[0] = 1.f / 7.f; wt[1] = 3.f / 7.f; wt[2] = 3.f / 7.f;
    }
}

__global__ __launch_bounds__(256) void prep_kernel(
    const float* __restrict__ inp, const float* __restrict__ img,
    const float* __restrict__ wp, const float* __restrict__ w_comp)
{
    int bx = blockIdx.x;
    if (bx < 64) {
        int o = bx >> 1;
        int half = bx & 1;
        int p = threadIdx.x;
        const float kexp = -0.28782313662425575f;  // -ln(10000)/32
        float acc = 0.f;
        int cbase = half ? 32 : 0;
#pragma unroll
        for (int i = 0; i < 16; i++) {
            float dv = __expf((float)(2 * i) * kexp);
            float s, c;
            __sincosf((float)p * dv, &s, &c);
            acc += wp[o * 64 + cbase + 2 * i] * s + wp[o * 64 + cbase + 2 * i + 1] * c;
        }
        if (half == 0) g_PXo[o * 256 + p] = acc;
        else           g_PYo[o * 256 + p] = acc;
    } else if (bx < 576) {
        int idx = (bx - 64) * 256 + threadIdx.x;
        int b = idx >> 16;
        int pix = idx & 65535;
        const float* ip = inp + ((b * PC) << 16) + pix;
        float acc = 0.f;
#pragma unroll
        for (int c = 0; c < PC; c++)
            acc += __ldg(&w_comp[c]) * __ldg(&ip[c << 16]);
        g_S[(b << 16) + pix] = 1.f / (1.f + __expf(-acc));
    } else {
        int bb = bx - 576;
        int h = bb & 255;
        int bc = bb >> 8;
        int w = threadIdx.x;
        int jh[4], jw[4]; float wh[4], ww[4];
        make_taps(h, jh, wh);
        make_taps(w, jw, ww);
        const float* ip = img + bc * IMG * IMG;
        float acc = 0.f;
#pragma unroll
        for (int a = 0; a < 4; a++) {
            float row = 0.f;
#pragma unroll
            for (int t = 0; t < 4; t++) row += ww[t] * __ldg(&ip[jh[a] * IMG + jw[t]]);
            acc += wh[a] * row;
        }
        g_R[(bc * 256 + h) * 256 + w] = acc;
    }
}

// ---------------------------------------------------------------------------
// K2: gram tables
// ---------------------------------------------------------------------------
__global__ void tables_kernel(const float* __restrict__ w_img) {
    int bx = blockIdx.x, t = threadIdx.x;
    if (bx < 256) {
        __shared__ float sPY[32];
        if (t < 32) sPY[t] = g_PYo[t * 256 + bx];
        __syncthreads();
        float a = 0.f;
#pragma unroll
        for (int o = 0; o < 32; o++) a += sPY[o] * g_PXo[o * 256 + t];
        g_T1t[bx * 256 + t] = a;
    } else {
#pragma unroll
        for (int d = 0; d < 3; d++) {
            int q = min(max(t + 2 * (d - 1), 0), 255);
            float ax = 0.f, ay = 0.f;
#pragma unroll
            for (int o = 0; o < 32; o++) {
                ax += g_PXo[o * 256 + q] * g_PXo[o * 256 + t];
                ay += g_PYo[o * 256 + q] * g_PYo[o * 256 + t];
            }
            g_GX[d * 256 + t] = ax;
            g_GY[d * 256 + t] = ay;
        }
        if (t < 9) {
            int i = t / 3, j = t % 3;
            float a = 0.f;
#pragma unroll
            for (int o = 0; o < 32; o++) a += w_img[o * 3 + i] * w_img[o * 3 + j];
            g_M[t] = a;
        }
    }
}

// ---------------------------------------------------------------------------
// K3: phi kernel — 3-way di split: grid (512, 3), thread = (pixel, di-group).
//   Each thread computes 3 taps (dj=0..2) of its di row; mc amortized over 3.
// ---------------------------------------------------------------------------
__global__ __launch_bounds__(256) void phi_kernel() {
    const int g = blockIdx.y;                       // di = g
    int idx = blockIdx.x * 256 + threadIdx.x;       // 0..131071
    int b = idx >> 16;
    int h = (idx >> 8) & 255;
    int w = idx & 255;

    const float* Rb = g_R + ((b * 3) << 16);
    const float* Sb = g_S + (b << 16);
    const int ctr = (h << 8) + w;

    float r0 = __ldg(&Rb[ctr]);
    float r1 = __ldg(&Rb[65536 + ctr]);
    float r2 = __ldg(&Rb[131072 + ctr]);
    float mc0 = __ldg(&g_M[0]) * r0 + __ldg(&g_M[1]) * r1 + __ldg(&g_M[2]) * r2;
    float mc1 = __ldg(&g_M[3]) * r0 + __ldg(&g_M[4]) * r1 + __ldg(&g_M[5]) * r2;
    float mc2 = __ldg(&g_M[6]) * r0 + __ldg(&g_M[7]) * r1 + __ldg(&g_M[8]) * r2;

    const int hn = min(max(h + 2 * g - 2, 0), 255);
    const float gy = __ldg(&g_GY[g * 256 + h]);
    const float t1c = __ldg(&g_T1t[(hn << 8) + w]);

#pragma unroll
    for (int dj = 0; dj < 3; dj++) {
        int wn = min(max(w + 2 * dj - 2, 0), 255);
        int nb = (hn << 8) + wn;
        float fs = __ldg(&Rb[nb]) * mc0 + __ldg(&Rb[65536 + nb]) * mc1
                 + __ldg(&Rb[131072 + nb]) * mc2;
        fs += __ldg(&g_GX[dj * 256 + w]) + gy;
        fs += __ldg(&g_T1t[(h << 8) + wn]) + t1c;
        g_phi[(((b * 9 + g * 3 + dj) << 16)) + ctr] = fs * __ldg(&Sb[nb]);
    }
}

// ---------------------------------------------------------------------------
// K4: aggregation, stride-2 row QUAD + float4 channels, 128-thread blocks.
//   Block: 28(w) x 16(h) x 4(ch).  smem float4 sT[20][32] = 10.2 KB.
//   4 warps: loader rows ty+4r (r=0..4) — exactly 20, no conditionals.
//   ty -> base row r1 in {0,1,8,9}; outputs r1+{0,2,4,6} cover 0..15.
//   Batched LDGs, ONE barrier.
// ---------------------------------------------------------------------------
constexpr int TW = 28, TH = 16;
constexpr int SW = 32, SH = 20;
constexpr int CCH = 4;

__global__ __launch_bounds__(128) void agg_kernel(
    const float* __restrict__ inp, float* __restrict__ out)
{
    const int z  = blockIdx.z;
    const int b  = z >> 4;
    const int ch0 = (z & 15) * CCH;
    const int h0 = blockIdx.y * TH;
    const int w0 = blockIdx.x * TW;
    const int tid = threadIdx.x;
    const int tx = tid & 31;
    const int ty = tid >> 5;      // 0..3

    __shared__ float4 sT[SH][SW];   // 10.2 KB

    const int gw = w0 - 2 + tx;
    const bool vw = (unsigned)gw < (unsigned)PW;
    const int ibase = ((b * PC + ch0) << 16);

    // ---- batched inp loads: 5 rows per thread, no conditionals ----
    float4 vr[5];
#pragma unroll
    for (int r = 0; r < 5; r++) {
        const int gh = h0 - 2 + ty + 4 * r;
        const bool v = vw && ((unsigned)gh < (unsigned)PH);
        const int pofs = (gh << 8) + gw;
        vr[r].x = v ? __ldg(&inp[ibase + pofs]) : 0.f;
        vr[r].y = v ? __ldg(&inp[ibase + 65536 + pofs]) : 0.f;
        vr[r].z = v ? __ldg(&inp[ibase + 131072 + pofs]) : 0.f;
        vr[r].w = v ? __ldg(&inp[ibase + 196608 + pofs]) : 0.f;
    }

    // compute coords: stride-2 row quad
    const int r1 = ((ty >> 1) << 3) | (ty & 1);   // 0,1,8,9
    const int w = w0 + tx;
    const bool active = (tx < TW) && (w < PW);

    // ---- phi loads: 4 output rows x 9 ----
    float ph[4][9];
    if (active) {
        const float* pb = g_phi + ((b * 9) << 16) + ((h0 + r1) << 8) + w;
#pragma unroll
        for (int i = 0; i < 4; i++)
#pragma unroll
            for (int k = 0; k < 9; k++)
                ph[i][k] = __ldg(&pb[(k << 16) + (i << 9)]);
    }

    // ---- stage to smem ----
#pragma unroll
    for (int r = 0; r < 5; r++)
        sT[ty + 4 * r][tx] = vr[r];
    __syncthreads();

    // ---- compute: 6 tap rows x 3 cols LDS.128; out i uses taps j=i..i+2 ----
    if (active) {
        float4 acc[4];
#pragma unroll
        for (int i = 0; i < 4; i++) acc[i] = make_float4(0.f, 0.f, 0.f, 0.f);
#pragma unroll
        for (int j = 0; j < 6; j++) {
            const int srow = r1 + 2 * j;
            float4 t0 = sT[srow][tx];
            float4 t1 = sT[srow][tx + 2];
            float4 t2 = sT[srow][tx + 4];
#pragma unroll
            for (int i = 0; i < 4; i++) {
                if (j >= i && j <= i + 2) {
                    const int di = j - i;
                    const float p0 = ph[i][3 * di], p1 = ph[i][3 * di + 1], p2 = ph[i][3 * di + 2];
                    acc[i].x += p0 * t0.x + p1 * t1.x + p2 * t2.x;
                    acc[i].y += p0 * t0.y + p1 * t1.y + p2 * t2.y;
                    acc[i].z += p0 * t0.z + p1 * t1.z + p2 * t2.z;
                    acc[i].w += p0 * t0.w + p1 * t1.w + p2 * t2.w;
                }
            }
        }
        const int obase = ibase + ((h0 + r1) << 8) + w;
#pragma unroll
        for (int i = 0; i < 4; i++) {
            const int ro = obase + (i << 9);
            out[ro]          = acc[i].x;
            out[ro + 65536]  = acc[i].y;
            out[ro + 131072] = acc[i].z;
            out[ro + 196608] = acc[i].w;
        }
    }
}

// ---------------------------------------------------------------------------
extern "C" void kernel_launch(void* const* d_in, const int* in_sizes, int n_in,
                              void* d_out, int out_size)
{
    const float* inp    = (const float*)d_in[0];   // [2,64,256,256]
    const float* img    = (const float*)d_in[1];   // [2,3,512,512]
    const float* w_pos  = (const float*)d_in[2];   // [32,64]
    const float* w_img  = (const float*)d_in[3];   // [32,3]
    const float* w_comp = (const float*)d_in[4];   // [64]
    float* out = (float*)d_out;

    prep_kernel<<<2112, 256>>>(inp, img, w_pos, w_comp);
    tables_kernel<<<257, 256>>>(w_img);
    dim3 pgrid(512, 3);
    phi_kernel<<<pgrid, 256>>>();
    dim3 grid((PW + TW - 1) / TW, PH / TH, PB * 16);   // 10 x 16 x 32 = 5120
    agg_kernel<<<grid, 128>>>(inp, out);
}

// round 13
// speedup vs baseline: 1.0650x; 1.0650x over previous
#include <cuda_runtime.h>

constexpr int PB = 2, PC = 64, PH = 256, PW = 256, IMG = 512;

// Scratch (device globals)
__device__ float g_R[PB * 3 * PH * PW];   // resized img (3 ch)
__device__ float g_S[PB * PH * PW];       // sigmoid(inp . w_comp)
__device__ float g_PXo[32 * PW];          // pos basis [o][w]
__device__ float g_PYo[32 * PH];
__device__ float g_T1t[PH * PW];          // T1t[h][w] = sum_o PX[o,w]*PY[o,h]
__device__ float g_GX[3 * PW];
__device__ float g_GY[3 * PH];
__device__ float g_M[9];                  // w_img^T w_img
__device__ float g_phi[PB * 9 * PH * PW]; // per-neighbor weight, 4.7 MB

// ---------------------------------------------------------------------------
// K1: prep = pos basis (0..63) + sigmoid(S) (64..575) + resize (576..2111)
// ---------------------------------------------------------------------------
__device__ __forceinline__ void make_taps(int o, int* j, float* wt) {
    j[0] = 2 * o - 1; j[1] = 2 * o; j[2] = 2 * o + 1; j[3] = 2 * o + 2;
    wt[0] = 0.125f; wt[1] = 0.375f; wt[2] = 0.375f; wt[3] = 0.125f;
    if (o == 0) {
        j[0] = 0; wt[0] = 0.f;
        wt[1] = 3.f / 7.f; wt[2] = 3.f / 7.f; wt[3] = 1.f / 7.f;
    } else if (o == 255) {
        j[3] = 511; wt[3] = 0.f;
        wt[0] = 1.f / 7.f; wt[1] = 3.f / 7.f; wt[2] = 3.f / 7.f;
    }
}

__global__ __launch_bounds__(256) void prep_kernel(
    const float* __restrict__ inp, const float* __restrict__ img,
    const float* __restrict__ wp, const float* __restrict__ w_comp)
{
    int bx = blockIdx.x;
    if (bx < 64) {
        int o = bx >> 1;
        int half = bx & 1;
        int p = threadIdx.x;
        const float kexp = -0.28782313662425575f;  // -ln(10000)/32
        float acc = 0.f;
        int cbase = half ? 32 : 0;
#pragma unroll
        for (int i = 0; i < 16; i++) {
            float dv = __expf((float)(2 * i) * kexp);
            float s, c;
            __sincosf((float)p * dv, &s, &c);
            acc += wp[o * 64 + cbase + 2 * i] * s + wp[o * 64 + cbase + 2 * i + 1] * c;
        }
        if (half == 0) g_PXo[o * 256 + p] = acc;
        else           g_PYo[o * 256 + p] = acc;
    } else if (bx < 576) {
        int idx = (bx - 64) * 256 + threadIdx.x;
        int b = idx >> 16;
        int pix = idx & 65535;
        const float* ip = inp + ((b * PC) << 16) + pix;
        float acc = 0.f;
#pragma unroll
        for (int c = 0; c < PC; c++)
            acc += __ldg(&w_comp[c]) * __ldg(&ip[c << 16]);
        g_S[(b << 16) + pix] = 1.f / (1.f + __expf(-acc));
    } else {
        int bb = bx - 576;
        int h = bb & 255;
        int bc = bb >> 8;
        int w = threadIdx.x;
        int jh[4], jw[4]; float wh[4], ww[4];
        make_taps(h, jh, wh);
        make_taps(w, jw, ww);
        const float* ip = img + bc * IMG * IMG;
        float acc = 0.f;
#pragma unroll
        for (int a = 0; a < 4; a++) {
            float row = 0.f;
#pragma unroll
            for (int t = 0; t < 4; t++) row += ww[t] * __ldg(&ip[jh[a] * IMG + jw[t]]);
            acc += wh[a] * row;
        }
        g_R[(bc * 256 + h) * 256 + w] = acc;
    }
}

// ---------------------------------------------------------------------------
// K2: gram tables
// ---------------------------------------------------------------------------
__global__ void tables_kernel(const float* __restrict__ w_img) {
    int bx = blockIdx.x, t = threadIdx.x;
    if (bx < 256) {
        __shared__ float sPY[32];
        if (t < 32) sPY[t] = g_PYo[t * 256 + bx];
        __syncthreads();
        float a = 0.f;
#pragma unroll
        for (int o = 0; o < 32; o++) a += sPY[o] * g_PXo[o * 256 + t];
        g_T1t[bx * 256 + t] = a;
    } else {
#pragma unroll
        for (int d = 0; d < 3; d++) {
            int q = min(max(t + 2 * (d - 1), 0), 255);
            float ax = 0.f, ay = 0.f;
#pragma unroll
            for (int o = 0; o < 32; o++) {
                ax += g_PXo[o * 256 + q] * g_PXo[o * 256 + t];
                ay += g_PYo[o * 256 + q] * g_PYo[o * 256 + t];
            }
            g_GX[d * 256 + t] = ax;
            g_GY[d * 256 + t] = ay;
        }
        if (t < 9) {
            int i = t / 3, j = t % 3;
            float a = 0.f;
#pragma unroll
            for (int o = 0; o < 32; o++) a += w_img[o * 3 + i] * w_img[o * 3 + j];
            g_M[t] = a;
        }
    }
}

// ---------------------------------------------------------------------------
// K3: phi kernel — UNSPLIT: one thread per pixel, 9-neighbor loop (proven).
// ---------------------------------------------------------------------------
__global__ __launch_bounds__(256) void phi_kernel() {
    int idx = blockIdx.x * 256 + threadIdx.x;   // 0..131071
    int b = idx >> 16;
    int h = (idx >> 8) & 255;
    int w = idx & 255;

    const float* Rb = g_R + ((b * 3) << 16);
    const float* Sb = g_S + (b << 16);
    const int ctr = (h << 8) + w;

    float r0 = __ldg(&Rb[ctr]);
    float r1 = __ldg(&Rb[65536 + ctr]);
    float r2 = __ldg(&Rb[131072 + ctr]);
    float mc0 = __ldg(&g_M[0]) * r0 + __ldg(&g_M[1]) * r1 + __ldg(&g_M[2]) * r2;
    float mc1 = __ldg(&g_M[3]) * r0 + __ldg(&g_M[4]) * r1 + __ldg(&g_M[5]) * r2;
    float mc2 = __ldg(&g_M[6]) * r0 + __ldg(&g_M[7]) * r1 + __ldg(&g_M[8]) * r2;

#pragma unroll
    for (int k = 0; k < 9; k++) {
        int di = (k / 3), dj = (k % 3);
        int hn = min(max(h + 2 * di - 2, 0), 255);
        int wn = min(max(w + 2 * dj - 2, 0), 255);
        int nb = (hn << 8) + wn;
        float fs = __ldg(&Rb[nb]) * mc0 + __ldg(&Rb[65536 + nb]) * mc1
                 + __ldg(&Rb[131072 + nb]) * mc2;
        fs += __ldg(&g_GX[dj * 256 + w]) + __ldg(&g_GY[di * 256 + h]);
        fs += __ldg(&g_T1t[(h << 8) + wn]) + __ldg(&g_T1t[(hn << 8) + w]);
        g_phi[(((b * 9 + k) << 16)) + ctr] = fs * __ldg(&Sb[nb]);
    }
}

// ---------------------------------------------------------------------------
// K4: aggregation, stride-2 row QUAD + TWO float4 channel quads (CCH=8).
//   Block: 128 thr, tile 28(w) x 16(h) x 8(ch).  smem 2 x float4[20][32]=20.5KB.
//   Two-phase loading (quad0 ld->STS, quad1 ld->STS), phi loaded before
//   barrier, sequential quad compute (acc regs reused).  ONE barrier.
//   Halves phi re-read redundancy vs CCH=4 (8 groups instead of 16).
// ---------------------------------------------------------------------------
constexpr int TW = 28, TH = 16;
constexpr int SW = 32, SH = 20;
constexpr int CCH = 8;

__global__ __launch_bounds__(128) void agg_kernel(
    const float* __restrict__ inp, float* __restrict__ out)
{
    const int z  = blockIdx.z;
    const int b  = z >> 3;
    const int ch0 = (z & 7) * CCH;
    const int h0 = blockIdx.y * TH;
    const int w0 = blockIdx.x * TW;
    const int tid = threadIdx.x;
    const int tx = tid & 31;
    const int ty = tid >> 5;      // 0..3

    __shared__ float4 sT[2][SH][SW];   // 20.5 KB

    const int gw = w0 - 2 + tx;
    const bool vw = (unsigned)gw < (unsigned)PW;
    const int ibase = ((b * PC + ch0) << 16);

    // compute coords
    const int r1 = ((ty >> 1) << 3) | (ty & 1);   // 0,1,8,9
    const int w = w0 + tx;
    const bool active = (tx < TW) && (w < PW);

    // ---- phi loads first (independent, deep MLP) ----
    float ph[4][9];
    if (active) {
        const float* pb = g_phi + ((b * 9) << 16) + ((h0 + r1) << 8) + w;
#pragma unroll
        for (int i = 0; i < 4; i++)
#pragma unroll
            for (int k = 0; k < 9; k++)
                ph[i][k] = __ldg(&pb[(k << 16) + (i << 9)]);
    }

    // ---- two-phase inp loading: quad q covers ch0+4q .. ch0+4q+3 ----
#pragma unroll
    for (int q = 0; q < 2; q++) {
        float4 vr[5];
        const int qbase = ibase + ((4 * q) << 16);
#pragma unroll
        for (int r = 0; r < 5; r++) {
            const int gh = h0 - 2 + ty + 4 * r;
            const bool v = vw && ((unsigned)gh < (unsigned)PH);
            const int pofs = (gh << 8) + gw;
            vr[r].x = v ? __ldg(&inp[qbase + pofs]) : 0.f;
            vr[r].y = v ? __ldg(&inp[qbase + 65536 + pofs]) : 0.f;
            vr[r].z = v ? __ldg(&inp[qbase + 131072 + pofs]) : 0.f;
            vr[r].w = v ? __ldg(&inp[qbase + 196608 + pofs]) : 0.f;
        }
#pragma unroll
        for (int r = 0; r < 5; r++)
            sT[q][ty + 4 * r][tx] = vr[r];
    }
    __syncthreads();

    // ---- compute: sequential quads, acc registers reused ----
    if (active) {
        const int obase = ibase + ((h0 + r1) << 8) + w;
#pragma unroll
        for (int q = 0; q < 2; q++) {
            float4 acc[4];
#pragma unroll
            for (int i = 0; i < 4; i++) acc[i] = make_float4(0.f, 0.f, 0.f, 0.f);
#pragma unroll
            for (int j = 0; j < 6; j++) {
                const int srow = r1 + 2 * j;
                float4 t0 = sT[q][srow][tx];
                float4 t1 = sT[q][srow][tx + 2];
                float4 t2 = sT[q][srow][tx + 4];
#pragma unroll
                for (int i = 0; i < 4; i++) {
                    if (j >= i && j <= i + 2) {
                        const int di = j - i;
                        const float p0 = ph[i][3 * di], p1 = ph[i][3 * di + 1], p2 = ph[i][3 * di + 2];
                        acc[i].x += p0 * t0.x + p1 * t1.x + p2 * t2.x;
                        acc[i].y += p0 * t0.y + p1 * t1.y + p2 * t2.y;
                        acc[i].z += p0 * t0.z + p1 * t1.z + p2 * t2.z;
                        acc[i].w += p0 * t0.w + p1 * t1.w + p2 * t2.w;
                    }
                }
            }
            const int oq = obase + ((4 * q) << 16);
#pragma unroll
            for (int i = 0; i < 4; i++) {
                const int ro = oq + (i << 9);
                out[ro]          = acc[i].x;
                out[ro + 65536]  = acc[i].y;
                out[ro + 131072] = acc[i].z;
                out[ro + 196608] = acc[i].w;
            }
        }
    }
}

// ---------------------------------------------------------------------------
extern "C" void kernel_launch(void* const* d_in, const int* in_sizes, int n_in,
                              void* d_out, int out_size)
{
    const float* inp    = (const float*)d_in[0];   // [2,64,256,256]
    const float* img    = (const float*)d_in[1];   // [2,3,512,512]
    const float* w_pos  = (const float*)d_in[2];   // [32,64]
    const float* w_img  = (const float*)d_in[3];   // [32,3]
    const float* w_comp = (const float*)d_in[4];   // [64]
    float* out = (float*)d_out;

    prep_kernel<<<2112, 256>>>(inp, img, w_pos, w_comp);
    tables_kernel<<<257, 256>>>(w_img);
    phi_kernel<<<512, 256>>>();
    dim3 grid((PW + TW - 1) / TW, PH / TH, PB * 8);   // 10 x 16 x 16 = 2560
    agg_kernel<<<grid, 128>>>(inp, out);
}

// round 14
// speedup vs baseline: 1.0771x; 1.0113x over previous
#include <cuda_runtime.h>

constexpr int PB = 2, PC = 64, PH = 256, PW = 256, IMG = 512;

// Scratch (device globals)
__device__ float g_R[PB * 3 * PH * PW];   // resized img (3 ch)
__device__ float g_S[PB * PH * PW];       // sigmoid(inp . w_comp)
__device__ float g_PXo[32 * PW];          // pos basis [o][w]
__device__ float g_PYo[32 * PH];
__device__ float g_T1t[PH * PW];          // T1t[h][w] = sum_o PX[o,w]*PY[o,h]
__device__ float g_GX[3 * PW];
__device__ float g_GY[3 * PH];
__device__ float g_M[9];                  // w_img^T w_img
__device__ float g_phi[PB * 9 * PH * PW]; // per-neighbor weight, 4.7 MB

// ---------------------------------------------------------------------------
// K1: prep = pos basis (0..63) + sigmoid(S) (64..575) + resize (576..2111)
// ---------------------------------------------------------------------------
__device__ __forceinline__ void make_taps(int o, int* j, float* wt) {
    j[0] = 2 * o - 1; j[1] = 2 * o; j[2] = 2 * o + 1; j[3] = 2 * o + 2;
    wt[0] = 0.125f; wt[1] = 0.375f; wt[2] = 0.375f; wt[3] = 0.125f;
    if (o == 0) {
        j[0] = 0; wt[0] = 0.f;
        wt[1] = 3.f / 7.f; wt[2] = 3.f / 7.f; wt[3] = 1.f / 7.f;
    } else if (o == 255) {
        j[3] = 511; wt[3] = 0.f;
        wt[0] = 1.f / 7.f; wt[1] = 3.f / 7.f; wt[2] = 3.f / 7.f;
    }
}

__global__ __launch_bounds__(256) void prep_kernel(
    const float* __restrict__ inp, const float* __restrict__ img,
    const float* __restrict__ wp, const float* __restrict__ w_comp)
{
    int bx = blockIdx.x;
    if (bx < 64) {
        int o = bx >> 1;
        int half = bx & 1;
        int p = threadIdx.x;
        const float kexp = -0.28782313662425575f;  // -ln(10000)/32
        float acc = 0.f;
        int cbase = half ? 32 : 0;
#pragma unroll
        for (int i = 0; i < 16; i++) {
            float dv = __expf((float)(2 * i) * kexp);
            float s, c;
            __sincosf((float)p * dv, &s, &c);
            acc += wp[o * 64 + cbase + 2 * i] * s + wp[o * 64 + cbase + 2 * i + 1] * c;
        }
        if (half == 0) g_PXo[o * 256 + p] = acc;
        else           g_PYo[o * 256 + p] = acc;
    } else if (bx < 576) {
        int idx = (bx - 64) * 256 + threadIdx.x;
        int b = idx >> 16;
        int pix = idx & 65535;
        const float* ip = inp + ((b * PC) << 16) + pix;
        float acc = 0.f;
#pragma unroll
        for (int c = 0; c < PC; c++)
            acc += __ldg(&w_comp[c]) * __ldg(&ip[c << 16]);
        g_S[(b << 16) + pix] = 1.f / (1.f + __expf(-acc));
    } else {
        int bb = bx - 576;
        int h = bb & 255;
        int bc = bb >> 8;
        int w = threadIdx.x;
        int jh[4], jw[4]; float wh[4], ww[4];
        make_taps(h, jh, wh);
        make_taps(w, jw, ww);
        const float* ip = img + bc * IMG * IMG;
        float acc = 0.f;
#pragma unroll
        for (int a = 0; a < 4; a++) {
            float row = 0.f;
#pragma unroll
            for (int t = 0; t < 4; t++) row += ww[t] * __ldg(&ip[jh[a] * IMG + jw[t]]);
            acc += wh[a] * row;
        }
        g_R[(bc * 256 + h) * 256 + w] = acc;
    }
}

// ---------------------------------------------------------------------------
// K2: gram tables
// ---------------------------------------------------------------------------
__global__ void tables_kernel(const float* __restrict__ w_img) {
    int bx = blockIdx.x, t = threadIdx.x;
    if (bx < 256) {
        __shared__ float sPY[32];
        if (t < 32) sPY[t] = g_PYo[t * 256 + bx];
        __syncthreads();
        float a = 0.f;
#pragma unroll
        for (int o = 0; o < 32; o++) a += sPY[o] * g_PXo[o * 256 + t];
        g_T1t[bx * 256 + t] = a;
    } else {
#pragma unroll
        for (int d = 0; d < 3; d++) {
            int q = min(max(t + 2 * (d - 1), 0), 255);
            float ax = 0.f, ay = 0.f;
#pragma unroll
            for (int o = 0; o < 32; o++) {
                ax += g_PXo[o * 256 + q] * g_PXo[o * 256 + t];
                ay += g_PYo[o * 256 + q] * g_PYo[o * 256 + t];
            }
            g_GX[d * 256 + t] = ax;
            g_GY[d * 256 + t] = ay;
        }
        if (t < 9) {
            int i = t / 3, j = t % 3;
            float a = 0.f;
#pragma unroll
            for (int o = 0; o < 32; o++) a += w_img[o * 3 + i] * w_img[o * 3 + j];
            g_M[t] = a;
        }
    }
}

// ---------------------------------------------------------------------------
// K3: phi kernel — UNSPLIT: one thread per pixel, 9-neighbor loop (proven).
// ---------------------------------------------------------------------------
__global__ __launch_bounds__(256) void phi_kernel() {
    int idx = blockIdx.x * 256 + threadIdx.x;   // 0..131071
    int b = idx >> 16;
    int h = (idx >> 8) & 255;
    int w = idx & 255;

    const float* Rb = g_R + ((b * 3) << 16);
    const float* Sb = g_S + (b << 16);
    const int ctr = (h << 8) + w;

    float r0 = __ldg(&Rb[ctr]);
    float r1 = __ldg(&Rb[65536 + ctr]);
    float r2 = __ldg(&Rb[131072 + ctr]);
    float mc0 = __ldg(&g_M[0]) * r0 + __ldg(&g_M[1]) * r1 + __ldg(&g_M[2]) * r2;
    float mc1 = __ldg(&g_M[3]) * r0 + __ldg(&g_M[4]) * r1 + __ldg(&g_M[5]) * r2;
    float mc2 = __ldg(&g_M[6]) * r0 + __ldg(&g_M[7]) * r1 + __ldg(&g_M[8]) * r2;

#pragma unroll
    for (int k = 0; k < 9; k++) {
        int di = (k / 3), dj = (k % 3);
        int hn = min(max(h + 2 * di - 2, 0), 255);
        int wn = min(max(w + 2 * dj - 2, 0), 255);
        int nb = (hn << 8) + wn;
        float fs = __ldg(&Rb[nb]) * mc0 + __ldg(&Rb[65536 + nb]) * mc1
                 + __ldg(&Rb[131072 + nb]) * mc2;
        fs += __ldg(&g_GX[dj * 256 + w]) + __ldg(&g_GY[di * 256 + h]);
        fs += __ldg(&g_T1t[(h << 8) + wn]) + __ldg(&g_T1t[(hn << 8) + w]);
        g_phi[(((b * 9 + k) << 16)) + ctr] = fs * __ldg(&Sb[nb]);
    }
}

// ---------------------------------------------------------------------------
// K4: aggregation, stride-2 row QUAD + TWO float4 channel quads (CCH=8).
//   128 thr, tile 28(w) x 16(h) x 8(ch), smem 20.5 KB, grid 2560.
//   Register-peak fix: phi LDGs moved AFTER __syncthreads so ph[36] does not
//   overlap the vr load batch.  Sequential quad compute (acc reused).
// ---------------------------------------------------------------------------
constexpr int TW = 28, TH = 16;
constexpr int SW = 32, SH = 20;
constexpr int CCH = 8;

__global__ __launch_bounds__(128) void agg_kernel(
    const float* __restrict__ inp, float* __restrict__ out)
{
    const int z  = blockIdx.z;
    const int b  = z >> 3;
    const int ch0 = (z & 7) * CCH;
    const int h0 = blockIdx.y * TH;
    const int w0 = blockIdx.x * TW;
    const int tid = threadIdx.x;
    const int tx = tid & 31;
    const int ty = tid >> 5;      // 0..3

    __shared__ float4 sT[2][SH][SW];   // 20.5 KB

    const int gw = w0 - 2 + tx;
    const bool vw = (unsigned)gw < (unsigned)PW;
    const int ibase = ((b * PC + ch0) << 16);

    // ---- two-phase inp loading: quad q covers ch0+4q .. ch0+4q+3 ----
#pragma unroll
    for (int q = 0; q < 2; q++) {
        float4 vr[5];
        const int qbase = ibase + ((4 * q) << 16);
#pragma unroll
        for (int r = 0; r < 5; r++) {
            const int gh = h0 - 2 + ty + 4 * r;
            const bool v = vw && ((unsigned)gh < (unsigned)PH);
            const int pofs = (gh << 8) + gw;
            vr[r].x = v ? __ldg(&inp[qbase + pofs]) : 0.f;
            vr[r].y = v ? __ldg(&inp[qbase + 65536 + pofs]) : 0.f;
            vr[r].z = v ? __ldg(&inp[qbase + 131072 + pofs]) : 0.f;
            vr[r].w = v ? __ldg(&inp[qbase + 196608 + pofs]) : 0.f;
        }
#pragma unroll
        for (int r = 0; r < 5; r++)
            sT[q][ty + 4 * r][tx] = vr[r];
    }
    __syncthreads();

    // compute coords
    const int r1 = ((ty >> 1) << 3) | (ty & 1);   // 0,1,8,9
    const int w = w0 + tx;
    const bool active = (tx < TW) && (w < PW);

    // ---- phi loads (after barrier: ph[36] doesn't overlap vr batch) ----
    float ph[4][9];
    if (active) {
        const float* pb = g_phi + ((b * 9) << 16) + ((h0 + r1) << 8) + w;
#pragma unroll
        for (int i = 0; i < 4; i++)
#pragma unroll
            for (int k = 0; k < 9; k++)
                ph[i][k] = __ldg(&pb[(k << 16) + (i << 9)]);
    }

    // ---- compute: sequential quads, acc registers reused ----
    if (active) {
        const int obase = ibase + ((h0 + r1) << 8) + w;
#pragma unroll
        for (int q = 0; q < 2; q++) {
            float4 acc[4];
#pragma unroll
            for (int i = 0; i < 4; i++) acc[i] = make_float4(0.f, 0.f, 0.f, 0.f);
#pragma unroll
            for (int j = 0; j < 6; j++) {
                const int srow = r1 + 2 * j;
                float4 t0 = sT[q][srow][tx];
                float4 t1 = sT[q][srow][tx + 2];
                float4 t2 = sT[q][srow][tx + 4];
#pragma unroll
                for (int i = 0; i < 4; i++) {
                    if (j >= i && j <= i + 2) {
                        const int di = j - i;
                        const float p0 = ph[i][3 * di], p1 = ph[i][3 * di + 1], p2 = ph[i][3 * di + 2];
                        acc[i].x += p0 * t0.x + p1 * t1.x + p2 * t2.x;
                        acc[i].y += p0 * t0.y + p1 * t1.y + p2 * t2.y;
                        acc[i].z += p0 * t0.z + p1 * t1.z + p2 * t2.z;
                        acc[i].w += p0 * t0.w + p1 * t1.w + p2 * t2.w;
                    }
                }
            }
            const int oq = obase + ((4 * q) << 16);
#pragma unroll
            for (int i = 0; i < 4; i++) {
                const int ro = oq + (i << 9);
                out[ro]          = acc[i].x;
                out[ro + 65536]  = acc[i].y;
                out[ro + 131072] = acc[i].z;
                out[ro + 196608] = acc[i].w;
            }
        }
    }
}

// ---------------------------------------------------------------------------
extern "C" void kernel_launch(void* const* d_in, const int* in_sizes, int n_in,
                              void* d_out, int out_size)
{
    const float* inp    = (const float*)d_in[0];   // [2,64,256,256]
    const float* img    = (const float*)d_in[1];   // [2,3,512,512]
    const float* w_pos  = (const float*)d_in[2];   // [32,64]
    const float* w_img  = (const float*)d_in[3];   // [32,3]
    const float* w_comp = (const float*)d_in[4];   // [64]
    float* out = (float*)d_out;

    prep_kernel<<<2112, 256>>>(inp, img, w_pos, w_comp);
    tables_kernel<<<257, 256>>>(w_img);
    phi_kernel<<<512, 256>>>();
    dim3 grid((PW + TW - 1) / TW, PH / TH, PB * 8);   // 10 x 16 x 16 = 2560
    agg_kernel<<<grid, 128>>>(inp, out);
}